// round 8
// baseline (speedup 1.0000x reference)
#include <cuda_runtime.h>
#include <stdint.h>

#define BN      16384
#define IN_DIM  256
#define HID     128
#define NCLS    8
#define T_STEPS 64
#define BETA    0.9f

// Scratch (no cudaMalloc allowed)
__device__ float g_cur1[BN * HID];          // 8 MB
__device__ uint4 g_masks[T_STEPS * BN];     // 16 MB  [t][s] spike masks
__device__ float g_W1T[IN_DIM * HID];       // 128 KB W1 transposed: [k][h]

// packed fp32x2 FMA: per-32-bit-lane IEEE fma.rn.f32 — lanes are independent
static __device__ __forceinline__ void ffma2(unsigned long long& d,
                                             unsigned long long a,
                                             unsigned long long b)
{
    asm("fma.rn.f32x2 %0, %1, %2, %0;" : "+l"(d) : "l"(a), "l"(b));
}

static __device__ __forceinline__ unsigned long long fdup(float v)
{
    unsigned long long r;
    unsigned u = __float_as_uint(v);
    asm("mov.b64 %0, {%1, %1};" : "=l"(r) : "r"(u));
    return r;
}

// ---------------------------------------------------------------------------
// K0: W1T[k][h] = W1[h][k]
// ---------------------------------------------------------------------------
__global__ __launch_bounds__(256) void k0_w1t(const float* __restrict__ W1)
{
    int idx = blockIdx.x * 256 + threadIdx.x;
    int h = idx & (HID - 1);
    int k = idx >> 7;
    g_W1T[k * HID + h] = W1[h * IN_DIM + k];
}

// ---------------------------------------------------------------------------
// K1: cur1 = x @ W1^T + b1 with order-preserving FFMA2.
// acc lanes = (hid pair h0,h1); each lane is the SAME sequential-k fmaf chain
// as the scalar R7 kernel (bitwise identical). W pairs come free from the
// [k][h] tile; x is duplicated into both lanes via mov.b64 (alu pipe).
// CTA tile: 64 samples x 128 hid. K chunks of 32. 256 thr, 8s x 4h/thread.
// ---------------------------------------------------------------------------
#define XS_STRIDE 36

__global__ __launch_bounds__(256) void k1_fc1(const float* __restrict__ x,
                                              const float* __restrict__ b1)
{
    __shared__ float xs[64 * XS_STRIDE];
    __shared__ float ws[32 * HID];

    const int tid = threadIdx.x;
    const int bs  = blockIdx.x * 64;
    const int c   = tid & 7;
    const int r   = tid >> 3;

    const int xf0_s = tid >> 3,         xf0_k = (tid & 7) * 4;
    const int xf1_s = (256 + tid) >> 3, xf1_k = ((256 + tid) & 7) * 4;

    float4 px0, px1, pw[4];

    px0 = *(const float4*)&x[(bs + xf0_s) * IN_DIM + xf0_k];
    px1 = *(const float4*)&x[(bs + xf1_s) * IN_DIM + xf1_k];
#pragma unroll
    for (int i = 0; i < 4; i++) {
        int f  = i * 256 + tid;
        int kk = f >> 5;
        int h4 = (f & 31) * 4;
        pw[i] = *(const float4*)&g_W1T[kk * HID + h4];
    }

    // acc2[i2][j]: lanes (h = r*4 + 2*i2, r*4 + 2*i2 + 1) for sample c+8j
    unsigned long long acc2[2][8];
#pragma unroll
    for (int i = 0; i < 2; i++)
#pragma unroll
        for (int j = 0; j < 8; j++) acc2[i][j] = 0ull;

    for (int ch = 0; ch < IN_DIM / 32; ch++) {
        *(float4*)&xs[xf0_s * XS_STRIDE + xf0_k] = px0;
        *(float4*)&xs[xf1_s * XS_STRIDE + xf1_k] = px1;
#pragma unroll
        for (int i = 0; i < 4; i++) {
            int f  = i * 256 + tid;
            int kk = f >> 5;
            int h4 = (f & 31) * 4;
            *(float4*)&ws[kk * HID + h4] = pw[i];
        }
        __syncthreads();

        if (ch + 1 < IN_DIM / 32) {
            int kc = (ch + 1) * 32;
            px0 = *(const float4*)&x[(bs + xf0_s) * IN_DIM + kc + xf0_k];
            px1 = *(const float4*)&x[(bs + xf1_s) * IN_DIM + kc + xf1_k];
#pragma unroll
            for (int i = 0; i < 4; i++) {
                int f  = i * 256 + tid;
                int kk = f >> 5;
                int h4 = (f & 31) * 4;
                pw[i] = *(const float4*)&g_W1T[(kc + kk) * HID + h4];
            }
        }

#pragma unroll
        for (int k = 0; k < 32; k += 4) {
            float4 xv[8];
#pragma unroll
            for (int j = 0; j < 8; j++)
                xv[j] = *(const float4*)&xs[(c + 8 * j) * XS_STRIDE + k];
            // w pairs: .x = (h0,h1), .y = (h2,h3) at hid r*4, k = k+kk
            ulonglong2 wv[4];
#pragma unroll
            for (int kk = 0; kk < 4; kk++)
                wv[kk] = *(const ulonglong2*)&ws[(k + kk) * HID + r * 4];
#pragma unroll
            for (int kk = 0; kk < 4; kk++) {
#pragma unroll
                for (int j = 0; j < 8; j++) {
                    float xf = (kk == 0) ? xv[j].x : (kk == 1) ? xv[j].y
                             : (kk == 2) ? xv[j].z : xv[j].w;
                    unsigned long long xx = fdup(xf);
                    ffma2(acc2[0][j], xx, wv[kk].x);
                    ffma2(acc2[1][j], xx, wv[kk].y);
                }
            }
        }
        __syncthreads();
    }

    float4 b1v = *(const float4*)&b1[r * 4];
#pragma unroll
    for (int j = 0; j < 8; j++) {
        int s = bs + c + 8 * j;
        unsigned long long a0 = acc2[0][j], a1 = acc2[1][j];
        float4 o;
        o.x = __uint_as_float((unsigned)(a0 & 0xffffffffull)) + b1v.x;
        o.y = __uint_as_float((unsigned)(a0 >> 32))           + b1v.y;
        o.z = __uint_as_float((unsigned)(a1 & 0xffffffffull)) + b1v.z;
        o.w = __uint_as_float((unsigned)(a1 >> 32))           + b1v.w;
        *(float4*)&g_cur1[s * HID + r * 4] = o;
    }
}

// ---------------------------------------------------------------------------
// K2: layer-1 LIF recurrence + spike mask packing (ballot).
// ---------------------------------------------------------------------------
__global__ __launch_bounds__(256) void k2_lif1()
{
    __shared__ uint32_t sm[T_STEPS][8][4];

    const int tid  = threadIdx.x;
    const int w    = tid >> 5;
    const int lane = tid & 31;
    const int g    = w & 3;
    const int q    = w >> 2;
    const int sb   = blockIdx.x * 8 + q * 4;
    const int h    = g * 32 + lane;

    float cur[4], mem[4];
#pragma unroll
    for (int j = 0; j < 4; j++) {
        cur[j] = g_cur1[(sb + j) * HID + h];
        mem[j] = 0.0f;
    }

    for (int t = 0; t < T_STEPS; t++) {
#pragma unroll
        for (int j = 0; j < 4; j++) {
            float m  = mem[j];
            float rf = (m > 1.0f) ? 1.0f : 0.0f;
            m = fmaf(BETA, m, cur[j]) - rf;
            mem[j] = m;
            unsigned bal = __ballot_sync(0xffffffffu, m > 1.0f);
            if (lane == 0) sm[t][q * 4 + j][g] = bal;
        }
    }
    __syncthreads();

    for (int idx = tid; idx < T_STEPS * 8; idx += 256) {
        int t  = idx >> 3;
        int sl = idx & 7;
        g_masks[t * BN + blockIdx.x * 8 + sl] = *(const uint4*)&sm[t][sl][0];
    }
}

// ---------------------------------------------------------------------------
// K3: layer-2 LUT + LIF, work DIVIDED between 2 threads per sample.
// CTA = 64 samples x one class-half (4 classes). 128 threads.
// Thread p (=tid&1) handles mask words {2p, 2p+1}: 8 LDS.128 per t,
// masks loaded as coalesced uint2. One float2 shfl_xor rebuilds the exact
// R4 tree ((sg0+sg1)+(sg2+sg3)); thread p LIFs classes {2p, 2p+1}.
// LUT[16][256] float4 = 64 KB -> 3 CTAs/SM. grid = (BN/64)*2 = 512.
// ---------------------------------------------------------------------------
static __device__ __forceinline__ float4 f4add(float4 a, float4 b)
{
    return make_float4(a.x + b.x, a.y + b.y, a.z + b.z, a.w + b.w);
}

__global__ __launch_bounds__(128) void k3_lif2(const float* __restrict__ W2,
                                               const float* __restrict__ b2,
                                               float* __restrict__ out)
{
    extern __shared__ float lut[];   // [16][256] float4 (classes half*4..+3)
    const int tid  = threadIdx.x;
    const int half = blockIdx.x & 1;
    const int sb   = (blockIdx.x >> 1) * 64;
    const int p    = tid & 1;                 // word-pair / class-pair selector
    const int s    = sb + (tid >> 1);

    // Build LUT: thread owns 32 bytes of one chunk; W2 rows cached in regs.
    {
        const int chunk = tid >> 3;            // 0..15
        const int bbase = (tid & 7) * 32;
        float w[4][8];
#pragma unroll
        for (int cc = 0; cc < 4; cc++)
#pragma unroll
            for (int j = 0; j < 8; j++)
                w[cc][j] = W2[(half * 4 + cc) * HID + chunk * 8 + j];

        for (int i = 0; i < 32; i++) {
            int byt = bbase + i;
            float4 v = make_float4(0.f, 0.f, 0.f, 0.f);
#pragma unroll
            for (int j = 0; j < 8; j++) {
                if ((byt >> j) & 1) {
                    v.x += w[0][j]; v.y += w[1][j];
                    v.z += w[2][j]; v.w += w[3][j];
                }
            }
            *(float4*)&lut[(chunk * 256 + byt) * 4] = v;
        }
    }
    __syncthreads();

    const float b2a = b2[half * 4 + 2 * p];
    const float b2b = b2[half * 4 + 2 * p + 1];

    // masks as uint2: element (t*BN + s)*2 + p = words (2p, 2p+1)
    const uint2* mp = (const uint2*)g_masks + (size_t)s * 2 + p;

    uint2 m0 = mp[0];
    uint2 m1 = mp[(size_t)BN * 2];

    float mA = 0.f, mB = 0.f, aA = 0.f, aB = 0.f, rA = 0.f, rB = 0.f;
    const unsigned FULL = 0xffffffffu;

    for (int t = 0; t < T_STEPS; t++) {
        uint2 m = m0;
        m0 = m1;
        if (t + 2 < T_STEPS) m1 = mp[(size_t)(t + 2) * BN * 2];

        // two words: 2p (chunks 8p..8p+3) and 2p+1 (chunks 8p+4..8p+7)
        float4 part;
        {
            const float* lg0 = &lut[(p * 8 + 0) * 1024];
            const float* lg1 = &lut[(p * 8 + 4) * 1024];
            uint32_t w0 = m.x, w1 = m.y;
            float4 q0 = *(const float4*)&lg0[            ((w0        & 255u) << 2)];
            float4 q1 = *(const float4*)&lg0[1 * 1024 + (((w0 >> 8)  & 255u) << 2)];
            float4 q2 = *(const float4*)&lg0[2 * 1024 + (((w0 >> 16) & 255u) << 2)];
            float4 q3 = *(const float4*)&lg0[3 * 1024 + ((w0 >> 24)          << 2)];
            float4 sgA = f4add(f4add(q0, q1), f4add(q2, q3));
            float4 u0 = *(const float4*)&lg1[            ((w1        & 255u) << 2)];
            float4 u1 = *(const float4*)&lg1[1 * 1024 + (((w1 >> 8)  & 255u) << 2)];
            float4 u2 = *(const float4*)&lg1[2 * 1024 + (((w1 >> 16) & 255u) << 2)];
            float4 u3 = *(const float4*)&lg1[3 * 1024 + ((w1 >> 24)          << 2)];
            float4 sgB = f4add(f4add(u0, u1), f4add(u2, u3));
            part = f4add(sgA, sgB);          // (sg0+sg1) or (sg2+sg3)
        }

        // exchange: p=0 sends part.zw, keeps xy; p=1 sends part.xy, keeps zw
        float s0 = p ? part.x : part.z;
        float s1 = p ? part.y : part.w;
        float r0 = __shfl_xor_sync(FULL, s0, 1);
        float r1 = __shfl_xor_sync(FULL, s1, 1);
        float k0 = p ? part.z : part.x;
        float k1 = p ? part.w : part.y;
        float curA = (k0 + r0) + b2a;        // commutative: bitwise == R4 tree
        float curB = (k1 + r1) + b2b;

        mA = fmaf(BETA, mA, curA) - rA;
        mB = fmaf(BETA, mB, curB) - rB;
        rA = (mA > 1.0f) ? 1.0f : 0.0f;
        rB = (mB > 1.0f) ? 1.0f : 0.0f;
        aA += rA;
        aB += rB;
    }

    *(float2*)&out[s * 8 + half * 4 + 2 * p] = make_float2(aA, aB);
}

// ---------------------------------------------------------------------------
extern "C" void kernel_launch(void* const* d_in, const int* in_sizes, int n_in,
                              void* d_out, int out_size)
{
    const float* x  = (const float*)d_in[0];
    const float* W1 = (const float*)d_in[1];
    const float* b1 = (const float*)d_in[2];
    const float* W2 = (const float*)d_in[3];
    const float* b2 = (const float*)d_in[4];
    float* out = (float*)d_out;

    k0_w1t<<<(IN_DIM * HID) / 256, 256>>>(W1);
    k1_fc1<<<BN / 64, 256>>>(x, b1);
    k2_lif1<<<BN / 8, 256>>>();

    cudaFuncSetAttribute(k3_lif2, cudaFuncAttributeMaxDynamicSharedMemorySize, 65536);
    k3_lif2<<<(BN / 64) * 2, 128, 65536>>>(W2, b2, out);
}

// round 9
// speedup vs baseline: 1.4462x; 1.4462x over previous
#include <cuda_runtime.h>
#include <stdint.h>

#define BN      16384
#define IN_DIM  256
#define HID     128
#define NCLS    8
#define T_STEPS 64
#define BETA    0.9f
#define NSM     148

// Scratch (no cudaMalloc allowed)
__device__ float g_cur1[BN * HID];          // 8 MB
__device__ uint4 g_masks[T_STEPS * BN];     // 16 MB  [t][s] spike masks
__device__ float g_W1T[IN_DIM * HID];       // 128 KB W1 transposed: [k][h]

// ---------------------------------------------------------------------------
// K0: W1T[k][h] = W1[h][k]
// ---------------------------------------------------------------------------
__global__ __launch_bounds__(256) void k0_w1t(const float* __restrict__ W1)
{
    int idx = blockIdx.x * 256 + threadIdx.x;
    int h = idx & (HID - 1);
    int k = idx >> 7;
    g_W1T[k * HID + h] = W1[h * IN_DIM + k];
}

// ---------------------------------------------------------------------------
// K1: cur1 = x @ W1^T + b1. (R7 exact scalar version — bitwise-stable order.)
// ---------------------------------------------------------------------------
#define XS_STRIDE 36

__global__ __launch_bounds__(256) void k1_fc1(const float* __restrict__ x,
                                              const float* __restrict__ b1)
{
    __shared__ float xs[64 * XS_STRIDE];
    __shared__ float ws[32 * HID];

    const int tid = threadIdx.x;
    const int bs  = blockIdx.x * 64;
    const int c   = tid & 7;
    const int r   = tid >> 3;

    const int xf0_s = tid >> 3,         xf0_k = (tid & 7) * 4;
    const int xf1_s = (256 + tid) >> 3, xf1_k = ((256 + tid) & 7) * 4;

    float4 px0, px1, pw[4];

    px0 = *(const float4*)&x[(bs + xf0_s) * IN_DIM + xf0_k];
    px1 = *(const float4*)&x[(bs + xf1_s) * IN_DIM + xf1_k];
#pragma unroll
    for (int i = 0; i < 4; i++) {
        int f  = i * 256 + tid;
        int kk = f >> 5;
        int h4 = (f & 31) * 4;
        pw[i] = *(const float4*)&g_W1T[kk * HID + h4];
    }

    float acc[4][8];
#pragma unroll
    for (int i = 0; i < 4; i++)
#pragma unroll
        for (int j = 0; j < 8; j++) acc[i][j] = 0.0f;

    for (int ch = 0; ch < IN_DIM / 32; ch++) {
        *(float4*)&xs[xf0_s * XS_STRIDE + xf0_k] = px0;
        *(float4*)&xs[xf1_s * XS_STRIDE + xf1_k] = px1;
#pragma unroll
        for (int i = 0; i < 4; i++) {
            int f  = i * 256 + tid;
            int kk = f >> 5;
            int h4 = (f & 31) * 4;
            *(float4*)&ws[kk * HID + h4] = pw[i];
        }
        __syncthreads();

        if (ch + 1 < IN_DIM / 32) {
            int kc = (ch + 1) * 32;
            px0 = *(const float4*)&x[(bs + xf0_s) * IN_DIM + kc + xf0_k];
            px1 = *(const float4*)&x[(bs + xf1_s) * IN_DIM + kc + xf1_k];
#pragma unroll
            for (int i = 0; i < 4; i++) {
                int f  = i * 256 + tid;
                int kk = f >> 5;
                int h4 = (f & 31) * 4;
                pw[i] = *(const float4*)&g_W1T[(kc + kk) * HID + h4];
            }
        }

#pragma unroll
        for (int k = 0; k < 32; k += 4) {
            float4 xv[8];
#pragma unroll
            for (int j = 0; j < 8; j++)
                xv[j] = *(const float4*)&xs[(c + 8 * j) * XS_STRIDE + k];
            float4 wv[4];
#pragma unroll
            for (int kk = 0; kk < 4; kk++)
                wv[kk] = *(const float4*)&ws[(k + kk) * HID + r * 4];
#pragma unroll
            for (int kk = 0; kk < 4; kk++) {
                float w0 = wv[kk].x, w1 = wv[kk].y, w2 = wv[kk].z, w3 = wv[kk].w;
#pragma unroll
                for (int j = 0; j < 8; j++) {
                    float xvk = (kk == 0) ? xv[j].x : (kk == 1) ? xv[j].y
                              : (kk == 2) ? xv[j].z : xv[j].w;
                    acc[0][j] = fmaf(w0, xvk, acc[0][j]);
                    acc[1][j] = fmaf(w1, xvk, acc[1][j]);
                    acc[2][j] = fmaf(w2, xvk, acc[2][j]);
                    acc[3][j] = fmaf(w3, xvk, acc[3][j]);
                }
            }
        }
        __syncthreads();
    }

    float4 b1v = *(const float4*)&b1[r * 4];
#pragma unroll
    for (int j = 0; j < 8; j++) {
        int s = bs + c + 8 * j;
        float4 o;
        o.x = acc[0][j] + b1v.x;
        o.y = acc[1][j] + b1v.y;
        o.z = acc[2][j] + b1v.z;
        o.w = acc[3][j] + b1v.w;
        *(float4*)&g_cur1[s * HID + r * 4] = o;
    }
}

// ---------------------------------------------------------------------------
// K2: layer-1 LIF recurrence + spike mask packing (ballot).
// ---------------------------------------------------------------------------
__global__ __launch_bounds__(256) void k2_lif1()
{
    __shared__ uint32_t sm[T_STEPS][8][4];

    const int tid  = threadIdx.x;
    const int w    = tid >> 5;
    const int lane = tid & 31;
    const int g    = w & 3;
    const int q    = w >> 2;
    const int sb   = blockIdx.x * 8 + q * 4;
    const int h    = g * 32 + lane;

    float cur[4], mem[4];
#pragma unroll
    for (int j = 0; j < 4; j++) {
        cur[j] = g_cur1[(sb + j) * HID + h];
        mem[j] = 0.0f;
    }

    for (int t = 0; t < T_STEPS; t++) {
#pragma unroll
        for (int j = 0; j < 4; j++) {
            float m  = mem[j];
            float rf = (m > 1.0f) ? 1.0f : 0.0f;
            m = fmaf(BETA, m, cur[j]) - rf;
            mem[j] = m;
            unsigned bal = __ballot_sync(0xffffffffu, m > 1.0f);
            if (lane == 0) sm[t][q * 4 + j][g] = bal;
        }
    }
    __syncthreads();

    for (int idx = tid; idx < T_STEPS * 8; idx += 256) {
        int t  = idx >> 3;
        int sl = idx & 7;
        g_masks[t * BN + blockIdx.x * 8 + sl] = *(const uint4*)&sm[t][sl][0];
    }
}

// ---------------------------------------------------------------------------
// K3: fused layer-2 LUT + LIF (R4 math, bitwise identical), improved:
//  - balanced grid: 148 blocks x 2 class-halves = 296 CTAs (exactly 2/SM),
//    block bi handles samples [bi*BN/148, (bi+1)*BN/148) (110 or 111).
//  - software pipeline: lookups for t+1 (depend only on masks) are issued
//    before the LIF update of step t; mask prefetch distance 2.
// LUT[16][256] float4 = 64 KB dyn smem. 128 threads, 1 sample/thread.
// ---------------------------------------------------------------------------
static __device__ __forceinline__ float4 f4add(float4 a, float4 b)
{
    return make_float4(a.x + b.x, a.y + b.y, a.z + b.z, a.w + b.w);
}

// exact R4 per-timestep current: ((sg0+sg1)+(sg2+sg3)) + b2v, sg = (q0+q1)+(q2+q3)
static __device__ __forceinline__ float4 lut_tree(const float* __restrict__ lut,
                                                  uint4 m, float4 b2v)
{
    uint32_t w[4] = {m.x, m.y, m.z, m.w};
    float4 sg[4];
#pragma unroll
    for (int g = 0; g < 4; g++) {
        const float* lg = &lut[g * 4096];
        uint32_t wg = w[g];
        float4 q0 = *(const float4*)&lg[            ((wg        & 255u) << 2)];
        float4 q1 = *(const float4*)&lg[1 * 1024 + (((wg >> 8)  & 255u) << 2)];
        float4 q2 = *(const float4*)&lg[2 * 1024 + (((wg >> 16) & 255u) << 2)];
        float4 q3 = *(const float4*)&lg[3 * 1024 + ((wg >> 24)          << 2)];
        sg[g] = f4add(f4add(q0, q1), f4add(q2, q3));
    }
    return f4add(f4add(f4add(sg[0], sg[1]), f4add(sg[2], sg[3])), b2v);
}

__global__ __launch_bounds__(128) void k3_lif2(const float* __restrict__ W2,
                                               const float* __restrict__ b2,
                                               float* __restrict__ out)
{
    extern __shared__ float lut[];   // [16][256] float4
    const int tid  = threadIdx.x;
    const int half = blockIdx.x & 1;
    const int bi   = blockIdx.x >> 1;          // 0..147

    // Build LUT (register-cached W2 rows; values identical to R4's build).
    {
        const int chunk = tid >> 3;            // 0..15
        const int bbase = (tid & 7) * 32;
        float w[4][8];
#pragma unroll
        for (int cc = 0; cc < 4; cc++)
#pragma unroll
            for (int j = 0; j < 8; j++)
                w[cc][j] = W2[(half * 4 + cc) * HID + chunk * 8 + j];

        for (int i = 0; i < 32; i++) {
            int byt = bbase + i;
            float4 v = make_float4(0.f, 0.f, 0.f, 0.f);
#pragma unroll
            for (int j = 0; j < 8; j++) {
                if ((byt >> j) & 1) {
                    v.x += w[0][j]; v.y += w[1][j];
                    v.z += w[2][j]; v.w += w[3][j];
                }
            }
            *(float4*)&lut[(chunk * 256 + byt) * 4] = v;
        }
    }
    __syncthreads();

    const int s_begin = (bi * BN) / NSM;
    const int s_end   = ((bi + 1) * BN) / NSM;
    const int s       = s_begin + tid;
    if (s >= s_end) return;

    float4 b2v = make_float4(b2[half * 4 + 0], b2[half * 4 + 1],
                             b2[half * 4 + 2], b2[half * 4 + 3]);

    const uint4* mp = &g_masks[s];

    uint4 mb = mp[BN];                       // mask for t = 1
    float4 cur = lut_tree(lut, mp[0], b2v);  // current for t = 0

    float4 mem = make_float4(0.f, 0.f, 0.f, 0.f);
    float4 acc = mem, rst = mem;

#pragma unroll 2
    for (int t = 0; t < T_STEPS - 1; t++) {
        // prefetch mask t+2 (clamped; issued before the dependent tree)
        int tp = (t + 2 < T_STEPS) ? (t + 2) : (T_STEPS - 1);
        uint4 mnew = mp[(size_t)tp * BN];

        // lookups for t+1 — independent of the LIF chain below
        float4 nxt = lut_tree(lut, mb, b2v);
        mb = mnew;

        // LIF for step t
        mem.x = fmaf(BETA, mem.x, cur.x) - rst.x;
        mem.y = fmaf(BETA, mem.y, cur.y) - rst.y;
        mem.z = fmaf(BETA, mem.z, cur.z) - rst.z;
        mem.w = fmaf(BETA, mem.w, cur.w) - rst.w;
        rst.x = (mem.x > 1.0f) ? 1.0f : 0.0f;
        rst.y = (mem.y > 1.0f) ? 1.0f : 0.0f;
        rst.z = (mem.z > 1.0f) ? 1.0f : 0.0f;
        rst.w = (mem.w > 1.0f) ? 1.0f : 0.0f;
        acc.x += rst.x; acc.y += rst.y; acc.z += rst.z; acc.w += rst.w;

        cur = nxt;
    }

    // final step t = 63
    mem.x = fmaf(BETA, mem.x, cur.x) - rst.x;
    mem.y = fmaf(BETA, mem.y, cur.y) - rst.y;
    mem.z = fmaf(BETA, mem.z, cur.z) - rst.z;
    mem.w = fmaf(BETA, mem.w, cur.w) - rst.w;
    acc.x += (mem.x > 1.0f) ? 1.0f : 0.0f;
    acc.y += (mem.y > 1.0f) ? 1.0f : 0.0f;
    acc.z += (mem.z > 1.0f) ? 1.0f : 0.0f;
    acc.w += (mem.w > 1.0f) ? 1.0f : 0.0f;

    *(float4*)&out[s * 8 + half * 4] = acc;
}

// ---------------------------------------------------------------------------
extern "C" void kernel_launch(void* const* d_in, const int* in_sizes, int n_in,
                              void* d_out, int out_size)
{
    const float* x  = (const float*)d_in[0];
    const float* W1 = (const float*)d_in[1];
    const float* b1 = (const float*)d_in[2];
    const float* W2 = (const float*)d_in[3];
    const float* b2 = (const float*)d_in[4];
    float* out = (float*)d_out;

    k0_w1t<<<(IN_DIM * HID) / 256, 256>>>(W1);
    k1_fc1<<<BN / 64, 256>>>(x, b1);
    k2_lif1<<<BN / 8, 256>>>();

    cudaFuncSetAttribute(k3_lif2, cudaFuncAttributeMaxDynamicSharedMemorySize, 65536);
    k3_lif2<<<NSM * 2, 128, 65536>>>(W2, b2, out);
}